// round 14
// baseline (speedup 1.0000x reference)
#include <cuda_runtime.h>
#include <cuda_bf16.h>
#include <math.h>

#define DIM   1024
#define MD    2048
#define BT    128
#define LAMBF 0.3f
#define NITER 500
#define HPAR  0.005f
#define RMC   0.99f
#define INVH  0.01f
#define LOWACT 0.001f
#define LANM  128
#define NBLK  128

// smem layout (k_main): [0,64K) Ghi persist | [64K,128K) Glo persist
//                       [128K,192K) aT stages: st*32K + {hi:0, lo:16K}
#define SM_GLO   65536
#define SM_AST   131072
#define SM_ASTSZ 32768
#define SMEM_MMA 196608

// ---------------- device scratch ----------------
__device__ float g_G[MD * MD];
__device__ __nv_bfloat16 g_Ghi[MD * MD];
__device__ __nv_bfloat16 g_Glo[MD * MD];
__device__ __nv_bfloat16 g_aThi[BT * MD];   // a^T  [b][m]
__device__ __nv_bfloat16 g_aTlo[BT * MD];
__device__ float g_part[8 * MD * BT];       // split-K partials
__device__ float g_afp[MD * BT];            // a fp32 [m][b]
__device__ float g_c[MD * BT];
__device__ float g_res[DIM * BT];
__device__ float g_v0[MD];
__device__ float g_v1[MD];
__device__ float g_w[MD];
__device__ float g_alpha[LANM];
__device__ float g_beta[LANM + 1];
__device__ float g_apart[NBLK];
__device__ float g_scal[4];
__device__ float g_cn[MD];
__device__ float g_pre[MD];
__device__ float g_esum;
__device__ unsigned g_count;
__device__ unsigned g_gen;
// fine-grained sync counters
__device__ unsigned g_partc[16];
__device__ unsigned g_shrc[16];
__device__ unsigned g_rdc[8];

// ---------------- PTX helpers ----------------
__device__ __forceinline__ unsigned swz(unsigned x) { return x ^ ((x >> 3) & 0x70); }

__device__ __forceinline__ void mma_bf16(float* d, const unsigned* a, const unsigned* b) {
    asm volatile(
        "mma.sync.aligned.m16n8k16.row.col.f32.bf16.bf16.f32 "
        "{%0,%1,%2,%3}, {%4,%5,%6,%7}, {%8,%9}, {%0,%1,%2,%3};\n"
        : "+f"(d[0]), "+f"(d[1]), "+f"(d[2]), "+f"(d[3])
        : "r"(a[0]), "r"(a[1]), "r"(a[2]), "r"(a[3]), "r"(b[0]), "r"(b[1]));
}
__device__ __forceinline__ void ldsm4(unsigned* r, unsigned saddr) {
    asm volatile("ldmatrix.sync.aligned.m8n8.x4.shared.b16 {%0,%1,%2,%3}, [%4];\n"
                 : "=r"(r[0]), "=r"(r[1]), "=r"(r[2]), "=r"(r[3]) : "r"(saddr));
}
__device__ __forceinline__ void cpa16(unsigned dst, const void* src) {
    asm volatile("cp.async.cg.shared.global [%0], [%1], 16;\n" :: "r"(dst), "l"(src));
}
__device__ __forceinline__ unsigned ldacq(const unsigned* p) {
    unsigned v;
    asm volatile("ld.acquire.gpu.global.u32 %0, [%1];" : "=r"(v) : "l"(p));
    return v;
}

// software grid barrier (Lanczos phase only; all NBLK blocks co-resident)
__device__ __forceinline__ void gbar() {
    __threadfence();
    __syncthreads();
    if (threadIdx.x == 0) {
        unsigned gen = *((volatile unsigned*)&g_gen);
        if (atomicAdd(&g_count, 1u) == NBLK - 1u) {
            g_count = 0u;
            __threadfence();
            atomicExch(&g_gen, gen + 1u);
        } else {
            while (*((volatile unsigned*)&g_gen) == gen) { __nanosleep(32); }
        }
        __threadfence();
    }
    __syncthreads();
}

// ---------------- init / zero ----------------
__global__ void k_zero() {
    int idx = blockIdx.x * blockDim.x + threadIdx.x;
    int stride = gridDim.x * blockDim.x;
    for (int i = idx; i < MD * BT; i += stride) g_afp[i] = 0.f;
    unsigned* p1 = (unsigned*)g_aThi;
    unsigned* p2 = (unsigned*)g_aTlo;
    for (int i = idx; i < MD * BT / 2; i += stride) { p1[i] = 0u; p2[i] = 0u; }
    if (idx < MD) g_cn[idx] = 0.f;
    if (idx < 16) { g_partc[idx] = 0u; g_shrc[idx] = 0u; }
    if (idx < 8)  g_rdc[idx] = 0u;
    if (idx == 0) { g_esum = 0.f; g_count = 0u; g_gen = 0u; }
}

// ---------------- Gram: G[m][k] = sum_d A[d][m] A[d][k]  (+ bf16 hi/lo) ----------------
__global__ void __launch_bounds__(256) k_G(const float* __restrict__ A) {
    __shared__ float As[16][64];
    __shared__ float Bs[16][64];
    int tid = threadIdx.x;
    int m0 = blockIdx.y * 64, k0 = blockIdx.x * 64;
    int ty = tid >> 4, tx = tid & 15;
    float acc[4][4] = {};
    for (int d0 = 0; d0 < DIM; d0 += 16) {
#pragma unroll
        for (int i = 0; i < 4; i++) {
            int e = tid + 256 * i; int r = e >> 6, c = e & 63;
            As[r][c] = A[(size_t)(d0 + r) * MD + m0 + c];
            Bs[r][c] = A[(size_t)(d0 + r) * MD + k0 + c];
        }
        __syncthreads();
#pragma unroll
        for (int kk = 0; kk < 16; kk++) {
            float4 g  = *(float4*)&As[kk][ty * 4];
            float4 b4 = *(float4*)&Bs[kk][tx * 4];
            acc[0][0] += g.x * b4.x; acc[0][1] += g.x * b4.y; acc[0][2] += g.x * b4.z; acc[0][3] += g.x * b4.w;
            acc[1][0] += g.y * b4.x; acc[1][1] += g.y * b4.y; acc[1][2] += g.y * b4.z; acc[1][3] += g.y * b4.w;
            acc[2][0] += g.z * b4.x; acc[2][1] += g.z * b4.y; acc[2][2] += g.z * b4.z; acc[2][3] += g.z * b4.w;
            acc[3][0] += g.w * b4.x; acc[3][1] += g.w * b4.y; acc[3][2] += g.w * b4.z; acc[3][3] += g.w * b4.w;
        }
        __syncthreads();
    }
#pragma unroll
    for (int i = 0; i < 4; i++)
#pragma unroll
        for (int j = 0; j < 4; j++) {
            size_t idx = (size_t)(m0 + ty * 4 + i) * MD + k0 + tx * 4 + j;
            float v = acc[i][j];
            g_G[idx] = v;
            __nv_bfloat16 h = __float2bfloat16(v);
            g_Ghi[idx] = h;
            g_Glo[idx] = __float2bfloat16(v - __bfloat162float(h));
        }
}

// ---------------- c[m][b] = sum_d A[d][m] * I[b][d] ----------------
__global__ void __launch_bounds__(256) k_c(const float* __restrict__ A,
                                           const float* __restrict__ Iin) {
    __shared__ float As[16][64];
    __shared__ float Is[16][132];
    int tid = threadIdx.x;
    int m0 = blockIdx.x * 64;
    int tx = tid & 31, ty = tid >> 5;
    float acc[8][4] = {};
    for (int d0 = 0; d0 < DIM; d0 += 16) {
#pragma unroll
        for (int i = 0; i < 4; i++) {
            int e = tid + 256 * i; int r = e >> 6, c = e & 63;
            As[r][c] = A[(size_t)(d0 + r) * MD + m0 + c];
        }
        {
            int b = tid >> 1, half = tid & 1;
            const float* ip = &Iin[(size_t)b * DIM + d0 + half * 8];
            float4 v0 = *(const float4*)ip;
            float4 v1 = *(const float4*)(ip + 4);
            int dl = half * 8;
            Is[dl + 0][b] = v0.x; Is[dl + 1][b] = v0.y; Is[dl + 2][b] = v0.z; Is[dl + 3][b] = v0.w;
            Is[dl + 4][b] = v1.x; Is[dl + 5][b] = v1.y; Is[dl + 6][b] = v1.z; Is[dl + 7][b] = v1.w;
        }
        __syncthreads();
#pragma unroll
        for (int kk = 0; kk < 16; kk++) {
            float4 b4 = *(float4*)&Is[kk][tx * 4];
            float4 a0 = *(float4*)&As[kk][ty * 8];
            float4 a1 = *(float4*)&As[kk][ty * 8 + 4];
            acc[0][0] += a0.x * b4.x; acc[0][1] += a0.x * b4.y; acc[0][2] += a0.x * b4.z; acc[0][3] += a0.x * b4.w;
            acc[1][0] += a0.y * b4.x; acc[1][1] += a0.y * b4.y; acc[1][2] += a0.y * b4.z; acc[1][3] += a0.y * b4.w;
            acc[2][0] += a0.z * b4.x; acc[2][1] += a0.z * b4.y; acc[2][2] += a0.z * b4.z; acc[2][3] += a0.z * b4.w;
            acc[3][0] += a0.w * b4.x; acc[3][1] += a0.w * b4.y; acc[3][2] += a0.w * b4.z; acc[3][3] += a0.w * b4.w;
            acc[4][0] += a1.x * b4.x; acc[4][1] += a1.x * b4.y; acc[4][2] += a1.x * b4.z; acc[4][3] += a1.x * b4.w;
            acc[5][0] += a1.y * b4.x; acc[5][1] += a1.y * b4.y; acc[5][2] += a1.y * b4.z; acc[5][3] += a1.y * b4.w;
            acc[6][0] += a1.z * b4.x; acc[6][1] += a1.z * b4.y; acc[6][2] += a1.z * b4.z; acc[6][3] += a1.z * b4.w;
            acc[7][0] += a1.w * b4.x; acc[7][1] += a1.w * b4.y; acc[7][2] += a1.w * b4.z; acc[7][3] += a1.w * b4.w;
        }
        __syncthreads();
    }
#pragma unroll
    for (int i = 0; i < 8; i++)
#pragma unroll
        for (int j = 0; j < 4; j++)
            g_c[(size_t)(m0 + ty * 8 + i) * BT + tx * 4 + j] = acc[i][j];
}

__global__ void k_lan_init() {
    __shared__ float red[256];
    __shared__ float bc;
    int tid = threadIdx.x;
    float loc[8]; float ss = 0.f;
#pragma unroll
    for (int q = 0; q < 8; q++) {
        unsigned int i = tid + 256 * q;
        unsigned int u = (i + 1u) * 2654435761u;
        u ^= u >> 16; u *= 2246822519u; u ^= u >> 13;
        float r = (float)(u & 0xFFFFFFu) * (1.0f / 16777216.0f) - 0.5f;
        loc[q] = r; ss += r * r;
    }
    red[tid] = ss; __syncthreads();
    for (int o = 128; o > 0; o >>= 1) { if (tid < o) red[tid] += red[tid + o]; __syncthreads(); }
    if (tid == 0) bc = rsqrtf(red[0]);
    __syncthreads();
    float inv = bc;
#pragma unroll
    for (int q = 0; q < 8; q++) {
        int i = tid + 256 * q;
        g_v1[i] = loc[q] * inv;
        g_v0[i] = 0.f;
    }
    if (tid == 0) g_beta[0] = 0.f;
}

// ================= persistent mega-kernel: Lanczos + eig + 500 ISTA iters =================
__global__ void __launch_bounds__(256) k_main(float* __restrict__ out_a) {
    extern __shared__ char dynsmem[];
    unsigned sbase = (unsigned)__cvta_generic_to_shared(dynsmem);
    float* red = (float*)dynsmem;
    int tid = threadIdx.x;
    int bx = blockIdx.x;
    int wid = tid >> 5, lane = tid & 31;

    // ---------- Lanczos (128 steps) ----------
    for (int j = 0; j < LANM; j++) {
        {
            int row = tid >> 4, l = tid & 15;
            int m = bx * 16 + row;
            const float* Grow = &g_G[(size_t)m * MD];
            float s0 = 0.f, s1 = 0.f;
            for (int k = l; k < MD; k += 32) {
                s0 += Grow[k] * g_v1[k];
                s1 += Grow[k + 16] * g_v1[k + 16];
            }
            float s = s0 + s1;
            s += __shfl_xor_sync(0xffffffffu, s, 8);
            s += __shfl_xor_sync(0xffffffffu, s, 4);
            s += __shfl_xor_sync(0xffffffffu, s, 2);
            s += __shfl_xor_sync(0xffffffffu, s, 1);
            if (l == 0) { g_w[m] = s; red[row] = s * g_v1[m]; }
            __syncthreads();
            if (tid == 0) {
                float t = 0.f;
#pragma unroll
                for (int i = 0; i < 16; i++) t += red[i];
                g_apart[bx] = t;
            }
        }
        gbar();
        if (bx == 0) {
            float s = (tid < NBLK) ? g_apart[tid] : 0.f;
            red[tid] = s; __syncthreads();
            for (int o = 128; o > 0; o >>= 1) { if (tid < o) red[tid] += red[tid + o]; __syncthreads(); }
            float alpha = red[0];
            __syncthreads();
            float bprev = g_beta[j];
            float wv[8], v1v[8]; float nrm = 0.f;
#pragma unroll
            for (int q = 0; q < 8; q++) {
                int i = tid + 256 * q;
                v1v[q] = g_v1[i];
                float w = g_w[i] - alpha * v1v[q] - bprev * g_v0[i];
                wv[q] = w; nrm += w * w;
            }
            red[tid] = nrm; __syncthreads();
            for (int o = 128; o > 0; o >>= 1) { if (tid < o) red[tid] += red[tid + o]; __syncthreads(); }
            float bnew = sqrtf(red[0]);
            float inv = 1.f / fmaxf(bnew, 1e-20f);
#pragma unroll
            for (int q = 0; q < 8; q++) {
                int i = tid + 256 * q;
                g_v0[i] = v1v[q];
                g_v1[i] = wv[q] * inv;
            }
            if (tid == 0) { g_alpha[j] = alpha; g_beta[j + 1] = bnew; }
        }
        gbar();
    }
    // ---------- lambda_max via Sturm bisection ----------
    if (bx == 0 && tid == 0) {
        float hi = 0.f;
        for (int i = 0; i < LANM; i++) {
            float b0 = (i > 0) ? fabsf(g_beta[i]) : 0.f;
            float b1 = (i < LANM - 1) ? fabsf(g_beta[i + 1]) : 0.f;
            hi = fmaxf(hi, g_alpha[i] + b0 + b1);
        }
        float lo = 0.f;
        for (int it = 0; it < 60; it++) {
            float x = 0.5f * (lo + hi);
            int cnt = 0;
            float d = g_alpha[0] - x;
            if (d < 0.f) cnt++;
            for (int i = 1; i < LANM; i++) {
                if (fabsf(d) < 1e-30f) d = -1e-30f;
                d = (g_alpha[i] - x) - (g_beta[i] * g_beta[i]) / d;
                if (d < 0.f) cnt++;
            }
            if (cnt >= LANM) hi = x; else lo = x;
        }
        float L = 0.5f * (lo + hi);
        g_scal[0] = L; g_scal[1] = 1.f / L; g_scal[2] = LAMBF / L;
    }
    gbar();

    // ---------- ISTA loop (fine-grained sync; G persistent in smem) ----------
    int mb = bx >> 3, ks = bx & 7;
    int ks0 = mb >> 1;
    int m0 = mb * 128;
    int k0 = ks * 256;
    int wm = wid >> 1, wn = wid & 1;
    int alr = (lane & 7) + ((lane >> 3) & 1) * 8;
    int alk = (lane >> 4) * 16;
    int blr = (lane & 7) + ((lane >> 4) & 1) * 8;
    int blk = ((lane >> 3) & 1) * 16;
    float eta = g_scal[1], thr = g_scal[2];
    float* pout = g_part + (size_t)ks * (MD * BT);
    int sb_b = tid & 127;
    int sb_m = mb * 128 + ks * 16 + (tid >> 7) * 8;

    // one-time load of this block's G slice (hi+lo, 128 rows x 256 k) into smem
#pragma unroll
    for (int e = tid; e < 4096; e += 256) {
        int r = e >> 5, s2 = e & 31;
        int c = s2 >> 3, s = s2 & 7;
        unsigned off = (unsigned)(c * 16384) + swz((unsigned)(r * 128 + s * 16));
        size_t go = (size_t)(m0 + r) * MD + k0 + s2 * 8;
        cpa16(sbase + off,          g_Ghi + go);
        cpa16(sbase + SM_GLO + off, g_Glo + go);
    }
    asm volatile("cp.async.commit_group;\n" ::: "memory");
    asm volatile("cp.async.wait_group 0;\n" ::: "memory");
    __syncthreads();

    for (int it = 0; it < NITER; it++) {
        unsigned b8 = 8u * (unsigned)it;
        // wait: aT (a^it) ready for this K-chunk
        if (it > 0) {
            if (tid == 0) {
                while (ldacq(&g_shrc[2 * ks]) < b8) __nanosleep(32);
                while (ldacq(&g_shrc[2 * ks + 1]) < b8) __nanosleep(32);
            }
            __syncthreads();
        }

        float acc[2][8][4];
#pragma unroll
        for (int i = 0; i < 2; i++)
#pragma unroll
            for (int j2 = 0; j2 < 8; j2++)
#pragma unroll
                for (int q = 0; q < 4; q++) acc[i][j2][q] = 0.f;

        // load aT chunk 0 into stage 0
        {
            unsigned ab = sbase + SM_AST;
            int ke = k0;
#pragma unroll
            for (int i = 0; i < 4; i++) {
                int e = tid + 256 * i;
                int r = e >> 3, s = e & 7;
                unsigned off = swz((unsigned)(r * 128 + s * 16));
                size_t ao = (size_t)r * MD + ke + s * 8;
                cpa16(ab + off,         g_aThi + ao);
                cpa16(ab + 16384 + off, g_aTlo + ao);
            }
            asm volatile("cp.async.commit_group;\n" ::: "memory");
        }
        int stage = 0;
#pragma unroll
        for (int ch = 0; ch < 4; ch++) {
            if (ch < 3) {
                unsigned ab = sbase + SM_AST + (stage ^ 1) * SM_ASTSZ;
                int ke = k0 + (ch + 1) * 64;
#pragma unroll
                for (int i = 0; i < 4; i++) {
                    int e = tid + 256 * i;
                    int r = e >> 3, s = e & 7;
                    unsigned off = swz((unsigned)(r * 128 + s * 16));
                    size_t ao = (size_t)r * MD + ke + s * 8;
                    cpa16(ab + off,         g_aThi + ao);
                    cpa16(ab + 16384 + off, g_aTlo + ao);
                }
                asm volatile("cp.async.commit_group;\n" ::: "memory");
                asm volatile("cp.async.wait_group 1;\n" ::: "memory");
            } else {
                asm volatile("cp.async.wait_group 0;\n" ::: "memory");
            }
            __syncthreads();
            // all gmem reads of a^it for this block complete once chunk 3 landed
            if (ch == 3 && tid == 0) atomicAdd(&g_rdc[ks], 1u);
            {
                unsigned gb_hi = sbase + ch * 16384;
                unsigned gb_lo = gb_hi + SM_GLO;
                unsigned ab_hi = sbase + SM_AST + stage * SM_ASTSZ;
                unsigned ab_lo = ab_hi + 16384;
#pragma unroll
                for (int s16 = 0; s16 < 4; s16++) {
                    int kb = s16 * 32;
                    unsigned Ah[2][4], Al[2][4], Bh[8][2], Bl[8][2];
#pragma unroll
                    for (int mi = 0; mi < 2; mi++) {
                        unsigned off = swz((unsigned)((wm * 32 + mi * 16 + alr) * 128 + kb + alk));
                        ldsm4(Ah[mi], gb_hi + off);
                        ldsm4(Al[mi], gb_lo + off);
                    }
#pragma unroll
                    for (int nj = 0; nj < 4; nj++) {
                        unsigned off = swz((unsigned)((wn * 64 + nj * 16 + blr) * 128 + kb + blk));
                        unsigned t[4];
                        ldsm4(t, ab_hi + off);
                        Bh[nj * 2][0] = t[0]; Bh[nj * 2][1] = t[1];
                        Bh[nj * 2 + 1][0] = t[2]; Bh[nj * 2 + 1][1] = t[3];
                        ldsm4(t, ab_lo + off);
                        Bl[nj * 2][0] = t[0]; Bl[nj * 2][1] = t[1];
                        Bl[nj * 2 + 1][0] = t[2]; Bl[nj * 2 + 1][1] = t[3];
                    }
#pragma unroll
                    for (int mi = 0; mi < 2; mi++)
#pragma unroll
                        for (int n8 = 0; n8 < 8; n8++) {
                            mma_bf16(acc[mi][n8], Ah[mi], Bh[n8]);
                            mma_bf16(acc[mi][n8], Ah[mi], Bl[n8]);
                            mma_bf16(acc[mi][n8], Al[mi], Bh[n8]);
                        }
                }
            }
            __syncthreads();
            stage ^= 1;
        }

        // wait: previous-iter shrink of mb done (its readers of our partial region finished)
        if (it > 0) {
            if (tid == 0) { while (ldacq(&g_shrc[mb]) < b8) __nanosleep(32); }
            __syncthreads();
        }
        // store partials (L2-only)
        {
            int r0 = m0 + wm * 32 + (lane >> 2);
            int c0 = wn * 64 + (lane & 3) * 2;
#pragma unroll
            for (int mi = 0; mi < 2; mi++)
#pragma unroll
                for (int n8 = 0; n8 < 8; n8++) {
                    int m = r0 + mi * 16, b = c0 + n8 * 8;
                    __stcg((float2*)&pout[(size_t)m * BT + b], make_float2(acc[mi][n8][0], acc[mi][n8][1]));
                    __stcg((float2*)&pout[(size_t)(m + 8) * BT + b], make_float2(acc[mi][n8][2], acc[mi][n8][3]));
                }
        }
        __threadfence();
        __syncthreads();
        if (tid == 0) atomicAdd(&g_partc[mb], 1u);

        // wait: all 8 partials of mb, and all 16 readers of chunk ks0 done with a^it
        if (tid == 0) {
            while (ldacq(&g_partc[mb]) < b8 + 8u) __nanosleep(32);
            while (ldacq(&g_rdc[ks0]) < 16u * (unsigned)(it + 1)) __nanosleep(32);
        }
        __syncthreads();
        // shrink rows [sb_m, sb_m+8) at column sb_b
        {
            float rv[8];
#pragma unroll
            for (int i = 0; i < 8; i++) {
                int m = sb_m + i;
                size_t idx = (size_t)m * BT + sb_b;
                float s = 0.f;
#pragma unroll
                for (int kk = 0; kk < 8; kk++)
                    s += __ldcg(&g_part[(size_t)kk * (MD * BT) + idx]);
                float v = g_afp[idx] + eta * (g_c[idx] - s);
                float av = fabsf(v) - thr;
                float r = (av > 0.f) ? copysignf(av, v) : 0.f;
                rv[i] = r;
                g_afp[idx] = r;
                if (it == NITER - 1) out_a[idx] = r;
            }
            unsigned hi4[4], lo4[4];
#pragma unroll
            for (int i = 0; i < 4; i++) {
                __nv_bfloat16 h0 = __float2bfloat16(rv[2 * i]);
                __nv_bfloat16 h1 = __float2bfloat16(rv[2 * i + 1]);
                float l0 = rv[2 * i]     - __bfloat162float(h0);
                float l1 = rv[2 * i + 1] - __bfloat162float(h1);
                __nv_bfloat16 g0 = __float2bfloat16(l0);
                __nv_bfloat16 g1 = __float2bfloat16(l1);
                hi4[i] = (unsigned)__bfloat16_as_ushort(h0) | ((unsigned)__bfloat16_as_ushort(h1) << 16);
                lo4[i] = (unsigned)__bfloat16_as_ushort(g0) | ((unsigned)__bfloat16_as_ushort(g1) << 16);
            }
            *(uint4*)&g_aThi[(size_t)sb_b * MD + sb_m] = *(uint4*)hi4;
            *(uint4*)&g_aTlo[(size_t)sb_b * MD + sb_m] = *(uint4*)lo4;
        }
        __threadfence();
        __syncthreads();
        if (tid == 0) atomicAdd(&g_shrc[mb], 1u);
    }
}

// ---------------- epilogue ----------------
__global__ void k_means(const float* __restrict__ a, const float* __restrict__ hes_in,
                        const float* __restrict__ l1_in, float* __restrict__ hes_out,
                        float* __restrict__ l1_out) {
    int w = (blockIdx.x * blockDim.x + threadIdx.x) >> 5;
    int lane = threadIdx.x & 31;
    if (w >= MD) return;
    float s1 = 0.f, s2 = 0.f;
    const float* row = a + (size_t)w * BT;
    for (int c = lane; c < BT; c += 32) { float v = row[c]; s1 += fabsf(v); s2 += v * v; }
    for (int o = 16; o; o >>= 1) {
        s1 += __shfl_xor_sync(0xffffffffu, s1, o);
        s2 += __shfl_xor_sync(0xffffffffu, s2, o);
    }
    if (lane == 0) {
        float nh = hes_in[w] * RMC + (s2 / BT) * INVH;
        hes_out[w] = nh;
        l1_out[w]  = l1_in[w] * RMC + (s1 / BT) * INVH;
        g_pre[w] = (HPAR / (float)BT) / (nh + LOWACT);
    }
}

__global__ void __launch_bounds__(256, 1) k_gemm(const float* __restrict__ Mp,
                                                 const float* __restrict__ xin,
                                                 const float* __restrict__ aux,
                                                 float* __restrict__ outp) {
    __shared__ float Gs[32][17];
    __shared__ float As[32][128];
    int tid = threadIdx.x;
    int m0 = blockIdx.x * 16;
    int kg = tid >> 6;
    int gt = tid & 63;
    int tx = gt & 15;
    int ty = gt >> 4;
    float acc[4][8] = {};
    for (int k0 = 0; k0 < MD; k0 += 32) {
        {
            int e = tid;
#pragma unroll
            for (int i = 0; i < 2; i++, e += 256) {
                int k = e & 31, r = e >> 5;
                Gs[k][r] = Mp[(size_t)(m0 + r) * MD + k0 + k];
            }
        }
#pragma unroll
        for (int i = 0; i < 4; i++) {
            int e4 = tid + 256 * i;
            int k = e4 >> 5, c4 = e4 & 31;
            *(float4*)&As[k][c4 * 4] = *(const float4*)&xin[(size_t)(k0 + k) * BT + c4 * 4];
        }
        __syncthreads();
        int kb = kg * 8;
#pragma unroll
        for (int kk = 0; kk < 8; kk++) {
            float4 al = *(float4*)&As[kb + kk][tx * 8];
            float4 ah = *(float4*)&As[kb + kk][tx * 8 + 4];
#pragma unroll
            for (int i = 0; i < 4; i++) {
                float g = Gs[kb + kk][ty * 4 + i];
                acc[i][0] += g * al.x; acc[i][1] += g * al.y;
                acc[i][2] += g * al.z; acc[i][3] += g * al.w;
                acc[i][4] += g * ah.x; acc[i][5] += g * ah.y;
                acc[i][6] += g * ah.z; acc[i][7] += g * ah.w;
            }
        }
        __syncthreads();
    }
    float* red = &As[0][0];
    if (kg >= 2) {
        float* dst = red + (kg - 2) * 2048;
#pragma unroll
        for (int i = 0; i < 4; i++)
#pragma unroll
            for (int j = 0; j < 8; j++)
                dst[(ty * 4 + i) * 128 + tx * 8 + j] = acc[i][j];
    }
    __syncthreads();
    if (kg < 2) {
        float* src = red + kg * 2048;
#pragma unroll
        for (int i = 0; i < 4; i++)
#pragma unroll
            for (int j = 0; j < 8; j++)
                acc[i][j] += src[(ty * 4 + i) * 128 + tx * 8 + j];
    }
    __syncthreads();
    if (kg == 1) {
#pragma unroll
        for (int i = 0; i < 4; i++)
#pragma unroll
            for (int j = 0; j < 8; j++)
                red[(ty * 4 + i) * 128 + tx * 8 + j] = acc[i][j];
    }
    __syncthreads();
    if (kg == 0) {
#pragma unroll
        for (int i = 0; i < 4; i++) {
            int m = m0 + ty * 4 + i;
#pragma unroll
            for (int j = 0; j < 8; j++) {
                int c = tx * 8 + j;
                float s = acc[i][j] + red[(ty * 4 + i) * 128 + c];
                outp[(size_t)m * BT + c] = aux[(size_t)c * DIM + m] - s;
            }
        }
    }
}

__global__ void __launch_bounds__(256) k_dB(const float* __restrict__ res,
                                            const float* __restrict__ a,
                                            const float* __restrict__ basis,
                                            float* __restrict__ nb) {
    __shared__ float Rs[32][33];
    __shared__ float As2[32][65];
    __shared__ float colred[64];
    int tid = threadIdx.x;
    int d0 = blockIdx.y * 32, m0 = blockIdx.x * 64;
    int tx = tid & 15, ty = tid >> 4;
    float acc[2][4] = {};
    for (int b0 = 0; b0 < BT; b0 += 32) {
#pragma unroll
        for (int i = 0; i < 4; i++) {
            int e = tid + 256 * i; int bb = e & 31, r = e >> 5;
            Rs[bb][r] = res[(size_t)(d0 + r) * BT + b0 + bb];
        }
#pragma unroll
        for (int i = 0; i < 8; i++) {
            int e = tid + 256 * i; int bb = e & 31, c = e >> 5;
            As2[bb][c] = a[(size_t)(m0 + c) * BT + b0 + bb];
        }
        __syncthreads();
#pragma unroll
        for (int bb = 0; bb < 32; bb++) {
            float r0 = Rs[bb][ty * 2], r1 = Rs[bb][ty * 2 + 1];
            float a0v = As2[bb][tx * 4], a1v = As2[bb][tx * 4 + 1];
            float a2v = As2[bb][tx * 4 + 2], a3v = As2[bb][tx * 4 + 3];
            acc[0][0] += r0 * a0v; acc[0][1] += r0 * a1v; acc[0][2] += r0 * a2v; acc[0][3] += r0 * a3v;
            acc[1][0] += r1 * a0v; acc[1][1] += r1 * a1v; acc[1][2] += r1 * a2v; acc[1][3] += r1 * a3v;
        }
        __syncthreads();
    }
    if (tid < 64) colred[tid] = 0.f;
    __syncthreads();
    float cpart[4] = {};
#pragma unroll
    for (int i = 0; i < 2; i++) {
        int d = d0 + ty * 2 + i;
#pragma unroll
        for (int j = 0; j < 4; j++) {
            int m = m0 + tx * 4 + j;
            float v = basis[(size_t)d * MD + m] + g_pre[m] * acc[i][j];
            nb[(size_t)d * MD + m] = v;
            cpart[j] += v * v;
        }
    }
#pragma unroll
    for (int j = 0; j < 4; j++) atomicAdd(&colred[tx * 4 + j], cpart[j]);
    __syncthreads();
    if (tid < 64) atomicAdd(&g_cn[m0 + tid], colred[tid]);
}

__global__ void k_norm(float* __restrict__ nb) {
    int idx = blockIdx.x * blockDim.x + threadIdx.x;
    int m = idx & (MD - 1);
    nb[idx] *= rsqrtf(g_cn[m]);
}

__global__ void k_esum(const float* __restrict__ I) {
    __shared__ float red[256];
    int tid = threadIdx.x;
    float s = 0.f;
    for (int i = blockIdx.x * 256 + tid; i < BT * DIM; i += gridDim.x * 256) {
        float v = I[i]; s += v * v;
    }
    red[tid] = s; __syncthreads();
    for (int o = 128; o; o >>= 1) { if (tid < o) red[tid] += red[tid + o]; __syncthreads(); }
    if (tid == 0) atomicAdd(&g_esum, red[0]);
}

__global__ void k_fin(const float* sig, const float* noi, float* snr_out) {
    snr_out[0] = (sig[0] * RMC + g_esum * INVH) / (noi[0] * RMC);
}

// ---------------- host ----------------
extern "C" void kernel_launch(void* const* d_in, const int* in_sizes, int n_in,
                              void* d_out, int out_size) {
    const float* I     = (const float*)d_in[0];
    const float* basis = (const float*)d_in[1];
    const float* hes   = (const float*)d_in[2];
    const float* l1    = (const float*)d_in[3];
    const float* sig   = (const float*)d_in[4];
    const float* noi   = (const float*)d_in[5];
    float* out = (float*)d_out;
    float* out_a   = out;
    float* out_b   = out_a + MD * BT;
    float* out_hes = out_b + DIM * MD;
    float* out_l1  = out_hes + MD;
    float* out_snr = out_l1 + MD;

    float* pres;
    cudaGetSymbolAddress((void**)&pres, g_res);

    cudaFuncSetAttribute(k_main, cudaFuncAttributeMaxDynamicSharedMemorySize, SMEM_MMA);

    k_zero<<<256, 256>>>();
    k_G<<<dim3(32, 32), 256>>>(basis);
    k_c<<<32, 256>>>(basis, I);
    k_lan_init<<<1, 256>>>();
    k_main<<<NBLK, 256, SMEM_MMA>>>(out_a);
    k_means<<<256, 256>>>(out_a, hes, l1, out_hes, out_l1);
    k_gemm<<<64, 256>>>(basis, out_a, I, pres);
    k_dB<<<dim3(32, 32), 256>>>(pres, out_a, basis, out_b);
    k_norm<<<2048, 1024>>>(out_b);
    k_esum<<<64, 256>>>(I);
    k_fin<<<1, 1>>>(sig, noi, out_snr);
}

// round 16
// speedup vs baseline: 1.4515x; 1.4515x over previous
#include <cuda_runtime.h>
#include <cuda_bf16.h>
#include <math.h>

#define DIM   1024
#define MD    2048
#define BT    128
#define LAMBF 0.3f
#define NITER 500
#define HPAR  0.005f
#define RMC   0.99f
#define INVH  0.01f
#define LOWACT 0.001f
#define LANM  128
#define NBLK  128

// ---------------- device scratch ----------------
__device__ float g_G[MD * MD];
__device__ __nv_bfloat16 g_Ghi[MD * MD];
__device__ __nv_bfloat16 g_Glo[MD * MD];
__device__ __nv_bfloat16 g_aThi[2 * BT * MD];   // ping-pong a^T [b][m]
__device__ __nv_bfloat16 g_aTlo[2 * BT * MD];
__device__ float g_part[2 * 8 * MD * BT];       // ping-pong split-K partials
__device__ float g_c[MD * BT];
__device__ float g_res[DIM * BT];
__device__ float g_v0[MD];
__device__ float g_v1[MD];
__device__ float g_w[MD];
__device__ float g_alpha[LANM];
__device__ float g_beta[LANM + 1];
__device__ float g_apart[NBLK];
__device__ float g_scal[4];
__device__ float g_cn[MD];
__device__ float g_pre[MD];
__device__ float g_esum;
__device__ unsigned g_count;
__device__ unsigned g_gen;
// fine-grained sync counters
__device__ unsigned g_partc[16];
__device__ unsigned g_shrc[16];
__device__ unsigned g_rdc[8];

// ---------------- PTX helpers ----------------
__device__ __forceinline__ unsigned swz(unsigned x) { return x ^ ((x >> 3) & 0x70); }

__device__ __forceinline__ void mma_bf16(float* d, const unsigned* a, const unsigned* b) {
    asm volatile(
        "mma.sync.aligned.m16n8k16.row.col.f32.bf16.bf16.f32 "
        "{%0,%1,%2,%3}, {%4,%5,%6,%7}, {%8,%9}, {%0,%1,%2,%3};\n"
        : "+f"(d[0]), "+f"(d[1]), "+f"(d[2]), "+f"(d[3])
        : "r"(a[0]), "r"(a[1]), "r"(a[2]), "r"(a[3]), "r"(b[0]), "r"(b[1]));
}
__device__ __forceinline__ void ldsm4(unsigned* r, unsigned saddr) {
    asm volatile("ldmatrix.sync.aligned.m8n8.x4.shared.b16 {%0,%1,%2,%3}, [%4];\n"
                 : "=r"(r[0]), "=r"(r[1]), "=r"(r[2]), "=r"(r[3]) : "r"(saddr));
}
__device__ __forceinline__ void cpa16(unsigned dst, const void* src) {
    asm volatile("cp.async.cg.shared.global [%0], [%1], 16;\n" :: "r"(dst), "l"(src));
}
__device__ __forceinline__ unsigned ldacq(const unsigned* p) {
    unsigned v;
    asm volatile("ld.acquire.gpu.global.u32 %0, [%1];" : "=r"(v) : "l"(p));
    return v;
}

// software grid barrier (Lanczos phase only; all NBLK blocks co-resident)
__device__ __forceinline__ void gbar() {
    __threadfence();
    __syncthreads();
    if (threadIdx.x == 0) {
        unsigned gen = *((volatile unsigned*)&g_gen);
        if (atomicAdd(&g_count, 1u) == NBLK - 1u) {
            g_count = 0u;
            __threadfence();
            atomicExch(&g_gen, gen + 1u);
        } else {
            while (*((volatile unsigned*)&g_gen) == gen) { __nanosleep(32); }
        }
        __threadfence();
    }
    __syncthreads();
}

// ---------------- init / zero ----------------
__global__ void k_zero() {
    int idx = blockIdx.x * blockDim.x + threadIdx.x;
    int stride = gridDim.x * blockDim.x;
    unsigned* p1 = (unsigned*)g_aThi;
    unsigned* p2 = (unsigned*)g_aTlo;
    for (int i = idx; i < MD * BT; i += stride) { p1[i] = 0u; p2[i] = 0u; }
    if (idx < MD) g_cn[idx] = 0.f;
    if (idx < 16) { g_partc[idx] = 0u; g_shrc[idx] = 0u; }
    if (idx < 8)  g_rdc[idx] = 0u;
    if (idx == 0) { g_esum = 0.f; g_count = 0u; g_gen = 0u; }
}

// ---------------- Gram: G[m][k] = sum_d A[d][m] A[d][k]  (+ bf16 hi/lo) ----------------
__global__ void __launch_bounds__(256) k_G(const float* __restrict__ A) {
    __shared__ float As[16][64];
    __shared__ float Bs[16][64];
    int tid = threadIdx.x;
    int m0 = blockIdx.y * 64, k0 = blockIdx.x * 64;
    int ty = tid >> 4, tx = tid & 15;
    float acc[4][4] = {};
    for (int d0 = 0; d0 < DIM; d0 += 16) {
#pragma unroll
        for (int i = 0; i < 4; i++) {
            int e = tid + 256 * i; int r = e >> 6, c = e & 63;
            As[r][c] = A[(size_t)(d0 + r) * MD + m0 + c];
            Bs[r][c] = A[(size_t)(d0 + r) * MD + k0 + c];
        }
        __syncthreads();
#pragma unroll
        for (int kk = 0; kk < 16; kk++) {
            float4 g  = *(float4*)&As[kk][ty * 4];
            float4 b4 = *(float4*)&Bs[kk][tx * 4];
            acc[0][0] += g.x * b4.x; acc[0][1] += g.x * b4.y; acc[0][2] += g.x * b4.z; acc[0][3] += g.x * b4.w;
            acc[1][0] += g.y * b4.x; acc[1][1] += g.y * b4.y; acc[1][2] += g.y * b4.z; acc[1][3] += g.y * b4.w;
            acc[2][0] += g.z * b4.x; acc[2][1] += g.z * b4.y; acc[2][2] += g.z * b4.z; acc[2][3] += g.z * b4.w;
            acc[3][0] += g.w * b4.x; acc[3][1] += g.w * b4.y; acc[3][2] += g.w * b4.z; acc[3][3] += g.w * b4.w;
        }
        __syncthreads();
    }
#pragma unroll
    for (int i = 0; i < 4; i++)
#pragma unroll
        for (int j = 0; j < 4; j++) {
            size_t idx = (size_t)(m0 + ty * 4 + i) * MD + k0 + tx * 4 + j;
            float v = acc[i][j];
            g_G[idx] = v;
            __nv_bfloat16 h = __float2bfloat16(v);
            g_Ghi[idx] = h;
            g_Glo[idx] = __float2bfloat16(v - __bfloat162float(h));
        }
}

// ---------------- c[m][b] = sum_d A[d][m] * I[b][d] ----------------
__global__ void __launch_bounds__(256) k_c(const float* __restrict__ A,
                                           const float* __restrict__ Iin) {
    __shared__ float As[16][64];
    __shared__ float Is[16][132];
    int tid = threadIdx.x;
    int m0 = blockIdx.x * 64;
    int tx = tid & 31, ty = tid >> 5;
    float acc[8][4] = {};
    for (int d0 = 0; d0 < DIM; d0 += 16) {
#pragma unroll
        for (int i = 0; i < 4; i++) {
            int e = tid + 256 * i; int r = e >> 6, c = e & 63;
            As[r][c] = A[(size_t)(d0 + r) * MD + m0 + c];
        }
        {
            int b = tid >> 1, half = tid & 1;
            const float* ip = &Iin[(size_t)b * DIM + d0 + half * 8];
            float4 v0 = *(const float4*)ip;
            float4 v1 = *(const float4*)(ip + 4);
            int dl = half * 8;
            Is[dl + 0][b] = v0.x; Is[dl + 1][b] = v0.y; Is[dl + 2][b] = v0.z; Is[dl + 3][b] = v0.w;
            Is[dl + 4][b] = v1.x; Is[dl + 5][b] = v1.y; Is[dl + 6][b] = v1.z; Is[dl + 7][b] = v1.w;
        }
        __syncthreads();
#pragma unroll
        for (int kk = 0; kk < 16; kk++) {
            float4 b4 = *(float4*)&Is[kk][tx * 4];
            float4 a0 = *(float4*)&As[kk][ty * 8];
            float4 a1 = *(float4*)&As[kk][ty * 8 + 4];
            acc[0][0] += a0.x * b4.x; acc[0][1] += a0.x * b4.y; acc[0][2] += a0.x * b4.z; acc[0][3] += a0.x * b4.w;
            acc[1][0] += a0.y * b4.x; acc[1][1] += a0.y * b4.y; acc[1][2] += a0.y * b4.z; acc[1][3] += a0.y * b4.w;
            acc[2][0] += a0.z * b4.x; acc[2][1] += a0.z * b4.y; acc[2][2] += a0.z * b4.z; acc[2][3] += a0.z * b4.w;
            acc[3][0] += a0.w * b4.x; acc[3][1] += a0.w * b4.y; acc[3][2] += a0.w * b4.z; acc[3][3] += a0.w * b4.w;
            acc[4][0] += a1.x * b4.x; acc[4][1] += a1.x * b4.y; acc[4][2] += a1.x * b4.z; acc[4][3] += a1.x * b4.w;
            acc[5][0] += a1.y * b4.x; acc[5][1] += a1.y * b4.y; acc[5][2] += a1.y * b4.z; acc[5][3] += a1.y * b4.w;
            acc[6][0] += a1.z * b4.x; acc[6][1] += a1.z * b4.y; acc[6][2] += a1.z * b4.z; acc[6][3] += a1.z * b4.w;
            acc[7][0] += a1.w * b4.x; acc[7][1] += a1.w * b4.y; acc[7][2] += a1.w * b4.z; acc[7][3] += a1.w * b4.w;
        }
        __syncthreads();
    }
#pragma unroll
    for (int i = 0; i < 8; i++)
#pragma unroll
        for (int j = 0; j < 4; j++)
            g_c[(size_t)(m0 + ty * 8 + i) * BT + tx * 4 + j] = acc[i][j];
}

__global__ void k_lan_init() {
    __shared__ float red[256];
    __shared__ float bc;
    int tid = threadIdx.x;
    float loc[8]; float ss = 0.f;
#pragma unroll
    for (int q = 0; q < 8; q++) {
        unsigned int i = tid + 256 * q;
        unsigned int u = (i + 1u) * 2654435761u;
        u ^= u >> 16; u *= 2246822519u; u ^= u >> 13;
        float r = (float)(u & 0xFFFFFFu) * (1.0f / 16777216.0f) - 0.5f;
        loc[q] = r; ss += r * r;
    }
    red[tid] = ss; __syncthreads();
    for (int o = 128; o > 0; o >>= 1) { if (tid < o) red[tid] += red[tid + o]; __syncthreads(); }
    if (tid == 0) bc = rsqrtf(red[0]);
    __syncthreads();
    float inv = bc;
#pragma unroll
    for (int q = 0; q < 8; q++) {
        int i = tid + 256 * q;
        g_v1[i] = loc[q] * inv;
        g_v0[i] = 0.f;
    }
    if (tid == 0) g_beta[0] = 0.f;
}

// ================= persistent mega-kernel: Lanczos + eig + 500 ISTA iters =================
__global__ void __launch_bounds__(256) k_main(float* __restrict__ out_a) {
    extern __shared__ char dynsmem[];
    unsigned sbase = (unsigned)__cvta_generic_to_shared(dynsmem);
    float* red = (float*)dynsmem;
    int tid = threadIdx.x;
    int bx = blockIdx.x;
    int wid = tid >> 5, lane = tid & 31;

    // ---------- Lanczos (128 steps) ----------
    for (int j = 0; j < LANM; j++) {
        {
            int row = tid >> 4, l = tid & 15;
            int m = bx * 16 + row;
            const float* Grow = &g_G[(size_t)m * MD];
            float s0 = 0.f, s1 = 0.f;
            for (int k = l; k < MD; k += 32) {
                s0 += Grow[k] * g_v1[k];
                s1 += Grow[k + 16] * g_v1[k + 16];
            }
            float s = s0 + s1;
            s += __shfl_xor_sync(0xffffffffu, s, 8);
            s += __shfl_xor_sync(0xffffffffu, s, 4);
            s += __shfl_xor_sync(0xffffffffu, s, 2);
            s += __shfl_xor_sync(0xffffffffu, s, 1);
            if (l == 0) { g_w[m] = s; red[row] = s * g_v1[m]; }
            __syncthreads();
            if (tid == 0) {
                float t = 0.f;
#pragma unroll
                for (int i = 0; i < 16; i++) t += red[i];
                g_apart[bx] = t;
            }
        }
        gbar();
        if (bx == 0) {
            float s = (tid < NBLK) ? g_apart[tid] : 0.f;
            red[tid] = s; __syncthreads();
            for (int o = 128; o > 0; o >>= 1) { if (tid < o) red[tid] += red[tid + o]; __syncthreads(); }
            float alpha = red[0];
            __syncthreads();
            float bprev = g_beta[j];
            float wv[8], v1v[8]; float nrm = 0.f;
#pragma unroll
            for (int q = 0; q < 8; q++) {
                int i = tid + 256 * q;
                v1v[q] = g_v1[i];
                float w = g_w[i] - alpha * v1v[q] - bprev * g_v0[i];
                wv[q] = w; nrm += w * w;
            }
            red[tid] = nrm; __syncthreads();
            for (int o = 128; o > 0; o >>= 1) { if (tid < o) red[tid] += red[tid + o]; __syncthreads(); }
            float bnew = sqrtf(red[0]);
            float inv = 1.f / fmaxf(bnew, 1e-20f);
#pragma unroll
            for (int q = 0; q < 8; q++) {
                int i = tid + 256 * q;
                g_v0[i] = v1v[q];
                g_v1[i] = wv[q] * inv;
            }
            if (tid == 0) { g_alpha[j] = alpha; g_beta[j + 1] = bnew; }
        }
        gbar();
    }
    // ---------- lambda_max via Sturm bisection ----------
    if (bx == 0 && tid == 0) {
        float hi = 0.f;
        for (int i = 0; i < LANM; i++) {
            float b0 = (i > 0) ? fabsf(g_beta[i]) : 0.f;
            float b1 = (i < LANM - 1) ? fabsf(g_beta[i + 1]) : 0.f;
            hi = fmaxf(hi, g_alpha[i] + b0 + b1);
        }
        float lo = 0.f;
        for (int it = 0; it < 60; it++) {
            float x = 0.5f * (lo + hi);
            int cnt = 0;
            float d = g_alpha[0] - x;
            if (d < 0.f) cnt++;
            for (int i = 1; i < LANM; i++) {
                if (fabsf(d) < 1e-30f) d = -1e-30f;
                d = (g_alpha[i] - x) - (g_beta[i] * g_beta[i]) / d;
                if (d < 0.f) cnt++;
            }
            if (cnt >= LANM) hi = x; else lo = x;
        }
        float L = 0.5f * (lo + hi);
        g_scal[0] = L; g_scal[1] = 1.f / L; g_scal[2] = LAMBF / L;
    }
    gbar();

    // ---------- ISTA loop (fine-grained sync, ping-pong aT + partials) ----------
    int mb = bx >> 3, ks = bx & 7;
    int ks0 = mb >> 1;
    int m0 = mb * 128;
    int k0 = ks * 256;
    int wm = wid >> 1, wn = wid & 1;
    int alr = (lane & 7) + ((lane >> 3) & 1) * 8;
    int alk = (lane >> 4) * 16;
    int blr = (lane & 7) + ((lane >> 4) & 1) * 8;
    int blk = ((lane >> 3) & 1) * 16;
    float eta = g_scal[1], thr = g_scal[2];
    int sb_b = tid & 127;
    int sb_m = mb * 128 + ks * 16 + (tid >> 7) * 8;

    // carry this block's a slice + c slice in registers
    float a_reg[8], c_reg[8];
#pragma unroll
    for (int i = 0; i < 8; i++) {
        a_reg[i] = 0.f;
        c_reg[i] = g_c[(size_t)(sb_m + i) * BT + sb_b];
    }

    for (int it = 0; it < NITER; it++) {
        unsigned b8 = 8u * (unsigned)it;
        int rb = it & 1, wb = rb ^ 1;
        const __nv_bfloat16* athi = g_aThi + (size_t)rb * (BT * MD);
        const __nv_bfloat16* atlo = g_aTlo + (size_t)rb * (BT * MD);
        float* pbase = g_part + (size_t)rb * (8 * MD * BT);
        float* pout  = pbase + (size_t)ks * (MD * BT);

        // wait: aT (a^it) ready for this K-chunk (true dependency)
        if (it > 0) {
            if (tid == 0) {
                while (ldacq(&g_shrc[2 * ks]) < b8) __nanosleep(32);
                while (ldacq(&g_shrc[2 * ks + 1]) < b8) __nanosleep(32);
            }
            __syncthreads();
        }

        float acc[2][8][4];
#pragma unroll
        for (int i = 0; i < 2; i++)
#pragma unroll
            for (int j2 = 0; j2 < 8; j2++)
#pragma unroll
                for (int q = 0; q < 4; q++) acc[i][j2][q] = 0.f;

        // load chunk 0
        {
            unsigned sb = sbase;
            int ke = k0;
#pragma unroll
            for (int i = 0; i < 4; i++) {
                int e = tid + 256 * i;
                int r = e >> 3, s2 = e & 7;
                unsigned off = swz((unsigned)(r * 128 + s2 * 16));
                size_t go = (size_t)(m0 + r) * MD + ke + s2 * 8;
                size_t ao = (size_t)r * MD + ke + s2 * 8;
                cpa16(sb + off,         g_Ghi + go);
                cpa16(sb + 16384 + off, g_Glo + go);
                cpa16(sb + 32768 + off, athi + ao);
                cpa16(sb + 49152 + off, atlo + ao);
            }
            asm volatile("cp.async.commit_group;\n" ::: "memory");
        }
        int stage = 0;
#pragma unroll
        for (int ch = 0; ch < 4; ch++) {
            if (ch < 3) {
                unsigned sb = sbase + (stage ^ 1) * 65536;
                int ke = k0 + (ch + 1) * 64;
#pragma unroll
                for (int i = 0; i < 4; i++) {
                    int e = tid + 256 * i;
                    int r = e >> 3, s2 = e & 7;
                    unsigned off = swz((unsigned)(r * 128 + s2 * 16));
                    size_t go = (size_t)(m0 + r) * MD + ke + s2 * 8;
                    size_t ao = (size_t)r * MD + ke + s2 * 8;
                    cpa16(sb + off,         g_Ghi + go);
                    cpa16(sb + 16384 + off, g_Glo + go);
                    cpa16(sb + 32768 + off, athi + ao);
                    cpa16(sb + 49152 + off, atlo + ao);
                }
                asm volatile("cp.async.commit_group;\n" ::: "memory");
                asm volatile("cp.async.wait_group 1;\n" ::: "memory");
            } else {
                asm volatile("cp.async.wait_group 0;\n" ::: "memory");
            }
            __syncthreads();
            // all gmem reads of a^it for this block are complete at ch==3
            if (ch == 3 && tid == 0) atomicAdd(&g_rdc[ks], 1u);
            {
                unsigned sb = sbase + stage * 65536;
#pragma unroll
                for (int s16 = 0; s16 < 4; s16++) {
                    int kb = s16 * 32;
                    unsigned Ah[2][4], Al[2][4], Bh[8][2], Bl[8][2];
#pragma unroll
                    for (int mi = 0; mi < 2; mi++) {
                        unsigned off = swz((unsigned)((wm * 32 + mi * 16 + alr) * 128 + kb + alk));
                        ldsm4(Ah[mi], sb + off);
                        ldsm4(Al[mi], sb + 16384 + off);
                    }
#pragma unroll
                    for (int nj = 0; nj < 4; nj++) {
                        unsigned off = swz((unsigned)((wn * 64 + nj * 16 + blr) * 128 + kb + blk));
                        unsigned t[4];
                        ldsm4(t, sb + 32768 + off);
                        Bh[nj * 2][0] = t[0]; Bh[nj * 2][1] = t[1];
                        Bh[nj * 2 + 1][0] = t[2]; Bh[nj * 2 + 1][1] = t[3];
                        ldsm4(t, sb + 49152 + off);
                        Bl[nj * 2][0] = t[0]; Bl[nj * 2][1] = t[1];
                        Bl[nj * 2 + 1][0] = t[2]; Bl[nj * 2 + 1][1] = t[3];
                    }
#pragma unroll
                    for (int mi = 0; mi < 2; mi++)
#pragma unroll
                        for (int n8 = 0; n8 < 8; n8++) {
                            mma_bf16(acc[mi][n8], Ah[mi], Bh[n8]);
                            mma_bf16(acc[mi][n8], Ah[mi], Bl[n8]);
                            mma_bf16(acc[mi][n8], Al[mi], Bh[n8]);
                        }
                }
            }
            __syncthreads();
            stage ^= 1;
        }

        // slack wait: shrink of iter it-2 for mb done (readers of this partial buffer finished)
        if (it >= 2) {
            if (tid == 0) { while (ldacq(&g_shrc[mb]) < b8 - 8u) __nanosleep(32); }
            __syncthreads();
        }
        // store partials (L2-only)
        {
            int r0 = m0 + wm * 32 + (lane >> 2);
            int c0 = wn * 64 + (lane & 3) * 2;
#pragma unroll
            for (int mi = 0; mi < 2; mi++)
#pragma unroll
                for (int n8 = 0; n8 < 8; n8++) {
                    int m = r0 + mi * 16, b = c0 + n8 * 8;
                    __stcg((float2*)&pout[(size_t)m * BT + b], make_float2(acc[mi][n8][0], acc[mi][n8][1]));
                    __stcg((float2*)&pout[(size_t)(m + 8) * BT + b], make_float2(acc[mi][n8][2], acc[mi][n8][3]));
                }
        }
        __threadfence();
        __syncthreads();
        if (tid == 0) atomicAdd(&g_partc[mb], 1u);

        // wait: all 8 partials of mb (true dep); readers of aT write-buffer done with a^{it-1} (slack)
        if (tid == 0) {
            while (ldacq(&g_partc[mb]) < b8 + 8u) __nanosleep(32);
            if (it > 0) while (ldacq(&g_rdc[ks0]) < 16u * (unsigned)it) __nanosleep(32);
        }
        __syncthreads();
        // shrink rows [sb_m, sb_m+8) at column sb_b; state carried in registers
        {
            __nv_bfloat16* wthi = g_aThi + (size_t)wb * (BT * MD);
            __nv_bfloat16* wtlo = g_aTlo + (size_t)wb * (BT * MD);
            unsigned hi4[4], lo4[4];
#pragma unroll
            for (int i = 0; i < 8; i++) {
                size_t idx = (size_t)(sb_m + i) * BT + sb_b;
                float s = 0.f;
#pragma unroll
                for (int kk = 0; kk < 8; kk++)
                    s += __ldcg(&pbase[(size_t)kk * (MD * BT) + idx]);
                float v = a_reg[i] + eta * (c_reg[i] - s);
                float av = fabsf(v) - thr;
                a_reg[i] = (av > 0.f) ? copysignf(av, v) : 0.f;
                if (it == NITER - 1) out_a[idx] = a_reg[i];
            }
#pragma unroll
            for (int i = 0; i < 4; i++) {
                __nv_bfloat16 h0 = __float2bfloat16(a_reg[2 * i]);
                __nv_bfloat16 h1 = __float2bfloat16(a_reg[2 * i + 1]);
                float l0 = a_reg[2 * i]     - __bfloat162float(h0);
                float l1 = a_reg[2 * i + 1] - __bfloat162float(h1);
                __nv_bfloat16 g0 = __float2bfloat16(l0);
                __nv_bfloat16 g1 = __float2bfloat16(l1);
                hi4[i] = (unsigned)__bfloat16_as_ushort(h0) | ((unsigned)__bfloat16_as_ushort(h1) << 16);
                lo4[i] = (unsigned)__bfloat16_as_ushort(g0) | ((unsigned)__bfloat16_as_ushort(g1) << 16);
            }
            *(uint4*)&wthi[(size_t)sb_b * MD + sb_m] = *(uint4*)hi4;
            *(uint4*)&wtlo[(size_t)sb_b * MD + sb_m] = *(uint4*)lo4;
        }
        __threadfence();
        __syncthreads();
        if (tid == 0) atomicAdd(&g_shrc[mb], 1u);
    }
}

// ---------------- epilogue ----------------
__global__ void k_means(const float* __restrict__ a, const float* __restrict__ hes_in,
                        const float* __restrict__ l1_in, float* __restrict__ hes_out,
                        float* __restrict__ l1_out) {
    int w = (blockIdx.x * blockDim.x + threadIdx.x) >> 5;
    int lane = threadIdx.x & 31;
    if (w >= MD) return;
    float s1 = 0.f, s2 = 0.f;
    const float* row = a + (size_t)w * BT;
    for (int c = lane; c < BT; c += 32) { float v = row[c]; s1 += fabsf(v); s2 += v * v; }
    for (int o = 16; o; o >>= 1) {
        s1 += __shfl_xor_sync(0xffffffffu, s1, o);
        s2 += __shfl_xor_sync(0xffffffffu, s2, o);
    }
    if (lane == 0) {
        float nh = hes_in[w] * RMC + (s2 / BT) * INVH;
        hes_out[w] = nh;
        l1_out[w]  = l1_in[w] * RMC + (s1 / BT) * INVH;
        g_pre[w] = (HPAR / (float)BT) / (nh + LOWACT);
    }
}

__global__ void __launch_bounds__(256, 1) k_gemm(const float* __restrict__ Mp,
                                                 const float* __restrict__ xin,
                                                 const float* __restrict__ aux,
                                                 float* __restrict__ outp) {
    __shared__ float Gs[32][17];
    __shared__ float As[32][128];
    int tid = threadIdx.x;
    int m0 = blockIdx.x * 16;
    int kg = tid >> 6;
    int gt = tid & 63;
    int tx = gt & 15;
    int ty = gt >> 4;
    float acc[4][8] = {};
    for (int k0 = 0; k0 < MD; k0 += 32) {
        {
            int e = tid;
#pragma unroll
            for (int i = 0; i < 2; i++, e += 256) {
                int k = e & 31, r = e >> 5;
                Gs[k][r] = Mp[(size_t)(m0 + r) * MD + k0 + k];
            }
        }
#pragma unroll
        for (int i = 0; i < 4; i++) {
            int e4 = tid + 256 * i;
            int k = e4 >> 5, c4 = e4 & 31;
            *(float4*)&As[k][c4 * 4] = *(const float4*)&xin[(size_t)(k0 + k) * BT + c4 * 4];
        }
        __syncthreads();
        int kb = kg * 8;
#pragma unroll
        for (int kk = 0; kk < 8; kk++) {
            float4 al = *(float4*)&As[kb + kk][tx * 8];
            float4 ah = *(float4*)&As[kb + kk][tx * 8 + 4];
#pragma unroll
            for (int i = 0; i < 4; i++) {
                float g = Gs[kb + kk][ty * 4 + i];
                acc[i][0] += g * al.x; acc[i][1] += g * al.y;
                acc[i][2] += g * al.z; acc[i][3] += g * al.w;
                acc[i][4] += g * ah.x; acc[i][5] += g * ah.y;
                acc[i][6] += g * ah.z; acc[i][7] += g * ah.w;
            }
        }
        __syncthreads();
    }
    float* red = &As[0][0];
    if (kg >= 2) {
        float* dst = red + (kg - 2) * 2048;
#pragma unroll
        for (int i = 0; i < 4; i++)
#pragma unroll
            for (int j = 0; j < 8; j++)
                dst[(ty * 4 + i) * 128 + tx * 8 + j] = acc[i][j];
    }
    __syncthreads();
    if (kg < 2) {
        float* src = red + kg * 2048;
#pragma unroll
        for (int i = 0; i < 4; i++)
#pragma unroll
            for (int j = 0; j < 8; j++)
                acc[i][j] += src[(ty * 4 + i) * 128 + tx * 8 + j];
    }
    __syncthreads();
    if (kg == 1) {
#pragma unroll
        for (int i = 0; i < 4; i++)
#pragma unroll
            for (int j = 0; j < 8; j++)
                red[(ty * 4 + i) * 128 + tx * 8 + j] = acc[i][j];
    }
    __syncthreads();
    if (kg == 0) {
#pragma unroll
        for (int i = 0; i < 4; i++) {
            int m = m0 + ty * 4 + i;
#pragma unroll
            for (int j = 0; j < 8; j++) {
                int c = tx * 8 + j;
                float s = acc[i][j] + red[(ty * 4 + i) * 128 + c];
                outp[(size_t)m * BT + c] = aux[(size_t)c * DIM + m] - s;
            }
        }
    }
}

__global__ void __launch_bounds__(256) k_dB(const float* __restrict__ res,
                                            const float* __restrict__ a,
                                            const float* __restrict__ basis,
                                            float* __restrict__ nb) {
    __shared__ float Rs[32][33];
    __shared__ float As2[32][65];
    __shared__ float colred[64];
    int tid = threadIdx.x;
    int d0 = blockIdx.y * 32, m0 = blockIdx.x * 64;
    int tx = tid & 15, ty = tid >> 4;
    float acc[2][4] = {};
    for (int b0 = 0; b0 < BT; b0 += 32) {
#pragma unroll
        for (int i = 0; i < 4; i++) {
            int e = tid + 256 * i; int bb = e & 31, r = e >> 5;
            Rs[bb][r] = res[(size_t)(d0 + r) * BT + b0 + bb];
        }
#pragma unroll
        for (int i = 0; i < 8; i++) {
            int e = tid + 256 * i; int bb = e & 31, c = e >> 5;
            As2[bb][c] = a[(size_t)(m0 + c) * BT + b0 + bb];
        }
        __syncthreads();
#pragma unroll
        for (int bb = 0; bb < 32; bb++) {
            float r0 = Rs[bb][ty * 2], r1 = Rs[bb][ty * 2 + 1];
            float a0v = As2[bb][tx * 4], a1v = As2[bb][tx * 4 + 1];
            float a2v = As2[bb][tx * 4 + 2], a3v = As2[bb][tx * 4 + 3];
            acc[0][0] += r0 * a0v; acc[0][1] += r0 * a1v; acc[0][2] += r0 * a2v; acc[0][3] += r0 * a3v;
            acc[1][0] += r1 * a0v; acc[1][1] += r1 * a1v; acc[1][2] += r1 * a2v; acc[1][3] += r1 * a3v;
        }
        __syncthreads();
    }
    if (tid < 64) colred[tid] = 0.f;
    __syncthreads();
    float cpart[4] = {};
#pragma unroll
    for (int i = 0; i < 2; i++) {
        int d = d0 + ty * 2 + i;
#pragma unroll
        for (int j = 0; j < 4; j++) {
            int m = m0 + tx * 4 + j;
            float v = basis[(size_t)d * MD + m] + g_pre[m] * acc[i][j];
            nb[(size_t)d * MD + m] = v;
            cpart[j] += v * v;
        }
    }
#pragma unroll
    for (int j = 0; j < 4; j++) atomicAdd(&colred[tx * 4 + j], cpart[j]);
    __syncthreads();
    if (tid < 64) atomicAdd(&g_cn[m0 + tid], colred[tid]);
}

__global__ void k_norm(float* __restrict__ nb) {
    int idx = blockIdx.x * blockDim.x + threadIdx.x;
    int m = idx & (MD - 1);
    nb[idx] *= rsqrtf(g_cn[m]);
}

__global__ void k_esum(const float* __restrict__ I) {
    __shared__ float red[256];
    int tid = threadIdx.x;
    float s = 0.f;
    for (int i = blockIdx.x * 256 + tid; i < BT * DIM; i += gridDim.x * 256) {
        float v = I[i]; s += v * v;
    }
    red[tid] = s; __syncthreads();
    for (int o = 128; o; o >>= 1) { if (tid < o) red[tid] += red[tid + o]; __syncthreads(); }
    if (tid == 0) atomicAdd(&g_esum, red[0]);
}

__global__ void k_fin(const float* sig, const float* noi, float* snr_out) {
    snr_out[0] = (sig[0] * RMC + g_esum * INVH) / (noi[0] * RMC);
}

// ---------------- host ----------------
#define SMEM_MMA 131072

extern "C" void kernel_launch(void* const* d_in, const int* in_sizes, int n_in,
                              void* d_out, int out_size) {
    const float* I     = (const float*)d_in[0];
    const float* basis = (const float*)d_in[1];
    const float* hes   = (const float*)d_in[2];
    const float* l1    = (const float*)d_in[3];
    const float* sig   = (const float*)d_in[4];
    const float* noi   = (const float*)d_in[5];
    float* out = (float*)d_out;
    float* out_a   = out;
    float* out_b   = out_a + MD * BT;
    float* out_hes = out_b + DIM * MD;
    float* out_l1  = out_hes + MD;
    float* out_snr = out_l1 + MD;

    float* pres;
    cudaGetSymbolAddress((void**)&pres, g_res);

    cudaFuncSetAttribute(k_main, cudaFuncAttributeMaxDynamicSharedMemorySize, SMEM_MMA);

    k_zero<<<256, 256>>>();
    k_G<<<dim3(32, 32), 256>>>(basis);
    k_c<<<32, 256>>>(basis, I);
    k_lan_init<<<1, 256>>>();
    k_main<<<NBLK, 256, SMEM_MMA>>>(out_a);
    k_means<<<256, 256>>>(out_a, hes, l1, out_hes, out_l1);
    k_gemm<<<64, 256>>>(basis, out_a, I, pres);
    k_dB<<<dim3(32, 32), 256>>>(pres, out_a, basis, out_b);
    k_norm<<<2048, 1024>>>(out_b);
    k_esum<<<64, 256>>>(I);
    k_fin<<<1, 1>>>(sig, noi, out_snr);
}